// round 14
// baseline (speedup 1.0000x reference)
#include <cuda_runtime.h>
#include <cuda_fp16.h>
#include <math.h>

// Problem constants (fixed by setup_inputs)
#define BB 4
#define PP 900
#define DD 512
#define HH 8
#define DK 64
#define NBH 32          // B*H
#define SIDE 30
#define C1 32           // conv1 out channels

// ---------------- scratch (device globals) ----------------
__device__ float g_q[BB*PP*DD];                   // [3600][512]
__device__ float g_k[BB*PP*DD];                   // [3600][512]
__device__ float g_scores[(size_t)NBH*PP*PP];     // [32][900][900]  (becomes attn in place)
__device__ int   g_idx[NBH*PP];                   // [32][900] column argmax
__device__ float g_pmax[NBH*8*PP];                // partial col-max per row-chunk
__device__ int   g_pidx[NBH*8*PP];
__device__ float g_part[BB*PP*15];                // [4][900][15] partial dot-products

// =====================================================================
// 1) Projection GEMM: C[m][n] = sum_k A[m][k] * W[n][k] + bias[n]
// =====================================================================
__global__ void proj_kernel(const float* __restrict__ A,
                            const float* __restrict__ W,
                            const float* __restrict__ bias,
                            int which)
{
    __shared__ float As[16][64];
    __shared__ float Bs[16][64];
    float* C = which ? g_k : g_q;

    int tid = threadIdx.x;
    int m0 = blockIdx.x * 64;
    int n0 = blockIdx.y * 64;
    int tx = tid & 15, ty = tid >> 4;

    float acc[4][4] = {};
    for (int k0 = 0; k0 < 512; k0 += 16) {
        #pragma unroll
        for (int i = 0; i < 4; i++) {
            int idx = tid + i * 256;
            int r = idx >> 4, kk = idx & 15;
            int m = m0 + r;
            As[kk][r] = (m < 3600) ? A[(size_t)m * 512 + k0 + kk] : 0.f;
            Bs[kk][r] = W[(size_t)(n0 + r) * 512 + k0 + kk];
        }
        __syncthreads();
        #pragma unroll
        for (int kk = 0; kk < 16; kk++) {
            float a[4], b[4];
            #pragma unroll
            for (int i = 0; i < 4; i++) a[i] = As[kk][ty * 4 + i];
            #pragma unroll
            for (int j = 0; j < 4; j++) b[j] = Bs[kk][tx * 4 + j];
            #pragma unroll
            for (int i = 0; i < 4; i++)
                #pragma unroll
                for (int j = 0; j < 4; j++)
                    acc[i][j] += a[i] * b[j];
        }
        __syncthreads();
    }
    #pragma unroll
    for (int i = 0; i < 4; i++) {
        int m = m0 + ty * 4 + i;
        if (m >= 3600) continue;
        #pragma unroll
        for (int j = 0; j < 4; j++) {
            int n = n0 + tx * 4 + j;
            C[(size_t)m * 512 + n] = acc[i][j] + bias[n];
        }
    }
}

// =====================================================================
// 2) scores[bh][p][w] = sum_c q[bh][p][c] * k[bh][w][c]   (K=64)
// =====================================================================
__global__ void scores_kernel()
{
    __shared__ float As[16][64];
    __shared__ float Bs[16][64];

    int z = blockIdx.z;
    int b = z >> 3, h = z & 7;
    const float* A  = g_q + (size_t)b * PP * DD + h * DK;
    const float* Bk = g_k + (size_t)b * PP * DD + h * DK;
    float* C = g_scores + (size_t)z * PP * PP;

    int tid = threadIdx.x;
    int m0 = blockIdx.x * 64;
    int n0 = blockIdx.y * 64;
    int tx = tid & 15, ty = tid >> 4;

    float acc[4][4] = {};
    for (int k0 = 0; k0 < 64; k0 += 16) {
        #pragma unroll
        for (int i = 0; i < 4; i++) {
            int idx = tid + i * 256;
            int r = idx >> 4, kk = idx & 15;
            As[kk][r] = (m0 + r < PP) ? A[(size_t)(m0 + r) * 512 + k0 + kk] : 0.f;
            Bs[kk][r] = (n0 + r < PP) ? Bk[(size_t)(n0 + r) * 512 + k0 + kk] : 0.f;
        }
        __syncthreads();
        #pragma unroll
        for (int kk = 0; kk < 16; kk++) {
            float a[4], b2[4];
            #pragma unroll
            for (int i = 0; i < 4; i++) a[i] = As[kk][ty * 4 + i];
            #pragma unroll
            for (int j = 0; j < 4; j++) b2[j] = Bs[kk][tx * 4 + j];
            #pragma unroll
            for (int i = 0; i < 4; i++)
                #pragma unroll
                for (int j = 0; j < 4; j++)
                    acc[i][j] += a[i] * b2[j];
        }
        __syncthreads();
    }
    #pragma unroll
    for (int i = 0; i < 4; i++) {
        int m = m0 + ty * 4 + i;
        if (m >= PP) continue;
        #pragma unroll
        for (int j = 0; j < 4; j++) {
            int n = n0 + tx * 4 + j;
            if (n < PP) C[(size_t)m * PP + n] = acc[i][j];
        }
    }
}

// =====================================================================
// 3) column argmax, two stages (validated in R4)
// =====================================================================
#define CHUNK 113   // 8 chunks: 7*113 + 109 = 900
__global__ void argmax_part_kernel()
{
    int bh = blockIdx.x;
    int ck = blockIdx.y;
    int r0 = ck * CHUNK;
    int len = min(CHUNK, PP - r0);
    const float* S0 = g_scores + (size_t)bh * PP * PP;
    for (int w = threadIdx.x; w < PP; w += 256) {
        const float* S = S0 + w;
        float best = -1e30f; int bi = 0;
        for (int r = 0; r < len; r++) {
            float v = S[(size_t)(r0 + r) * PP];
            if (v > best) { best = v; bi = r0 + r; }
        }
        g_pmax[(bh * 8 + ck) * PP + w] = best;
        g_pidx[(bh * 8 + ck) * PP + w] = bi;
    }
}

__global__ void argmax_reduce_kernel()
{
    int bh = blockIdx.x;
    int w = blockIdx.y * 256 + threadIdx.x;
    if (w >= PP) return;
    float best = -1e30f; int bi = 0;
    #pragma unroll
    for (int ck = 0; ck < 8; ck++) {
        float v = g_pmax[(bh * 8 + ck) * PP + w];
        if (v > best) { best = v; bi = g_pidx[(bh * 8 + ck) * PP + w]; }
    }
    g_idx[bh * PP + w] = bi;
}

// =====================================================================
// 4) gaussian modulation + /sqrt(dk) + row softmax, in place
// =====================================================================
__global__ void softmax_kernel()
{
    __shared__ float buf[PP];
    __shared__ float red[256];

    int row = blockIdx.x;
    int bh = row / PP, p0 = row % PP;
    int t = threadIdx.x;

    float ys0 = -1.f + (2.f / 29.f) * (float)(p0 / SIDE);
    float xs0 = -1.f + (2.f / 29.f) * (float)(p0 % SIDE);

    float* S = g_scores + (size_t)bh * PP * PP + (size_t)p0 * PP;
    const int* idx = g_idx + bh * PP;

    float lmax = -1e30f;
    for (int w = t; w < PP; w += 256) {
        int id = idx[w];
        float dy = ys0 - (float)(id / SIDE);
        float dx = xs0 - (float)(id % SIDE);
        float g = __expf(-(dx * dx + dy * dy) * (1.f / 50.f));
        float v = S[w] * g * 0.125f;
        buf[w] = v;
        lmax = fmaxf(lmax, v);
    }
    red[t] = lmax; __syncthreads();
    for (int s = 128; s > 0; s >>= 1) {
        if (t < s) red[t] = fmaxf(red[t], red[t + s]);
        __syncthreads();
    }
    float m = red[0];
    __syncthreads();

    float lsum = 0.f;
    for (int w = t; w < PP; w += 256) {
        float e = __expf(buf[w] - m);
        buf[w] = e;
        lsum += e;
    }
    red[t] = lsum; __syncthreads();
    for (int s = 128; s > 0; s >>= 1) {
        if (t < s) red[t] += red[t + s];
        __syncthreads();
    }
    float inv = 1.f / red[0];
    for (int w = t; w < PP; w += 256) S[w] = buf[w] * inv;
}

// =====================================================================
// common mma helpers (proven in R9/R10)
// =====================================================================
#define LO_SCALE 2048.0f
#define LO_INV   (1.0f / 2048.0f)

__device__ __forceinline__ void hmma_16x8x8(float& c0, float& c1, float& c2, float& c3,
                                            unsigned a0, unsigned a1, unsigned b0)
{
    asm volatile(
        "mma.sync.aligned.m16n8k8.row.col.f32.f16.f16.f32 "
        "{%0,%1,%2,%3}, {%4,%5}, {%6}, {%0,%1,%2,%3};\n"
        : "+f"(c0), "+f"(c1), "+f"(c2), "+f"(c3)
        : "r"(a0), "r"(a1), "r"(b0));
}

__device__ __forceinline__ unsigned pack_hh(__half a, __half b)
{
    __half2 h = __halves2half2(a, b);
    return *reinterpret_cast<unsigned*>(&h);
}

// hi = fp16(x); lo = fp16((x - hi) * 2048)
__device__ __forceinline__ void split2s(float a, float b, unsigned& hi, unsigned& lo)
{
    __half ha = __float2half_rn(a), hb = __float2half_rn(b);
    hi = pack_hh(ha, hb);
    lo = pack_hh(__float2half_rn((a - __half2float(ha)) * LO_SCALE),
                 __float2half_rn((b - __half2float(hb)) * LO_SCALE));
}

// =====================================================================
// 5) FUSED conv1 + conv2 + value-dot — R10-proven pieces only, NO swizzle.
//    Output tile 64 x 8.  Grid (15, 113, 4).  256 threads.
//
//    input  Xp  : rows rI=0..11  (gy = ty0-2+rI), cols jj=0..83 (gx = tx0-2+jj)
//    C1 records : [kc 0..3][rr*66+j]  rr=0..9 (gy = ty0-1+rr), j=0..65 (gx = tx0-1+j)
//                 16B record = 8 channels (kc*8 .. kc*8+7) as half2 pairs, hi + lo arrays
//    conv1 unit : C1 row rr, strip s (5 strips of 16 px, bound-checked j<66)
//    conv2 unit : warp = output row y (0..7); j0 = s*16+kx+g  (identical to R10)
// =====================================================================
#define FX_W      84
#define FX_ROWS   12
#define C1_ROWS   10
#define C1_W2     66
#define C1_NPIX   (C1_ROWS * C1_W2)      // 660

#define XH_OFF    0
#define XL_OFF    16128                  // 12*84*16
#define C1H_OFF   32256
#define C1L_OFF   74496                  // +4*660*16
#define W1H_OFF   116736
#define W1L_OFF   121344
#define W2H_OFF   125952
#define W2L_OFF   130560
#define SB1_OFF   135168
#define SB2_OFF   135296
#define FUSED_SMEM 135328

__global__ __launch_bounds__(256)
void fused_conv_kernel(const float* __restrict__ w1, const float* __restrict__ b1,
                       const float* __restrict__ w2, const float* __restrict__ b2,
                       const float* __restrict__ value)
{
    extern __shared__ char smem[];
    char* XpH = smem + XH_OFF;
    char* XpL = smem + XL_OFF;
    char* C1H = smem + C1H_OFF;
    char* C1L = smem + C1L_OFF;
    unsigned* W1H = (unsigned*)(smem + W1H_OFF);
    unsigned* W1L = (unsigned*)(smem + W1L_OFF);
    unsigned* W2H = (unsigned*)(smem + W2H_OFF);
    unsigned* W2L = (unsigned*)(smem + W2L_OFF);
    float* sb1 = (float*)(smem + SB1_OFF);
    float* sb2 = (float*)(smem + SB2_OFF);

    int n   = blockIdx.z;
    int ty0 = blockIdx.y * 8;
    int tx0 = blockIdx.x * 64;
    int tid = threadIdx.x;
    int wid = tid >> 5;
    int lane = tid & 31;
    int t = lane & 3;        // k-pair / oc-pair selector
    int g = lane >> 2;       // pixel row-in-fragment

    // ---- conv1 weight fragments (identical prep to R9/R10) ----
    for (int i = tid; i < 9 * 4 * 32; i += 256) {
        int tap = i >> 7;
        int nt  = (i >> 5) & 3;
        int ln  = i & 31;
        int lt = ln & 3, lg = ln >> 2;
        int oc1 = nt * 8 + lg;
        split2s(w1[oc1 * 72 + (2 * lt) * 9 + tap],
                w1[oc1 * 72 + (2 * lt + 1) * 9 + tap], W1H[i], W1L[i]);
        int ic0 = nt * 8 + 2 * lt;
        split2s(w2[lg * 288 + ic0 * 9 + tap],
                w2[lg * 288 + (ic0 + 1) * 9 + tap], W2H[i], W2L[i]);
    }
    if (tid < 32) sb1[tid] = b1[tid];
    if (tid < 8)  sb2[tid] = b2[tid];

    // ---- attn input tile (R9 loader, halo -2) ----
    for (int e = tid; e < FX_ROWS * FX_W; e += 256) {
        int rI = e / FX_W, jj = e % FX_W;
        int gy = ty0 - 2 + rI, gx = tx0 - 2 + jj;
        bool inb = ((unsigned)gy < (unsigned)PP) && ((unsigned)gx < (unsigned)PP);
        unsigned rh[4], rl[4];
        #pragma unroll
        for (int icp = 0; icp < 4; icp++) {
            float f0 = 0.f, f1 = 0.f;
            if (inb) {
                const float* base = g_scores + (((size_t)(n * 8 + 2 * icp)) * PP + gy) * PP + gx;
                f0 = base[0];
                f1 = base[(size_t)PP * PP];
            }
            split2s(f0, f1, rh[icp], rl[icp]);
        }
        *(uint4*)(XpH + e * 16) = make_uint4(rh[0], rh[1], rh[2], rh[3]);
        *(uint4*)(XpL + e * 16) = make_uint4(rl[0], rl[1], rl[2], rl[3]);
    }
    __syncthreads();

    // ================= conv1 phase (R9 unit, output -> smem records) =========
    {
        unsigned w1fh[9][4], w1fl[9][4];
        #pragma unroll
        for (int tap = 0; tap < 9; tap++)
            #pragma unroll
            for (int nt = 0; nt < 4; nt++) {
                w1fh[tap][nt] = W1H[(tap * 4 + nt) * 32 + lane];
                w1fl[tap][nt] = W1L[(tap * 4 + nt) * 32 + lane];
            }

        // 50 units: rr (0..9) x strip s (0..4)
        for (int it = wid; it < 50; it += 8) {
            int rr = it / 5, s = it % 5;
            float ah[4][4] = {};
            float al[4][4] = {};
            #pragma unroll
            for (int tap = 0; tap < 9; tap++) {
                int ky = tap / 3, kx = tap % 3;
                int j0 = s * 16 + kx + g;                 // input col jj
                int boff = ((rr + ky) * FX_W + j0) * 16 + t * 4;
                unsigned a0h = *(const unsigned*)(XpH + boff);
                unsigned a1h = *(const unsigned*)(XpH + boff + 8 * 16);
                unsigned a0l = *(const unsigned*)(XpL + boff);
                unsigned a1l = *(const unsigned*)(XpL + boff + 8 * 16);
                #pragma unroll
                for (int nt = 0; nt < 4; nt++) {
                    hmma_16x8x8(ah[nt][0], ah[nt][1], ah[nt][2], ah[nt][3], a0h, a1h, w1fh[tap][nt]);
                    hmma_16x8x8(al[nt][0], al[nt][1], al[nt][2], al[nt][3], a0l, a1l, w1fh[tap][nt]);
                    hmma_16x8x8(al[nt][0], al[nt][1], al[nt][2], al[nt][3], a0h, a1h, w1fl[tap][nt]);
                }
            }
            // epilogue: bias + relu; ZERO for out-of-image pixels; store records
            int gyr = ty0 - 1 + rr;
            bool rok = ((unsigned)gyr < (unsigned)PP);
            int jA = s * 16 + g;        // C1 col for c0,c1
            int jB = jA + 8;            // C1 col for c2,c3
            int gxA = tx0 - 1 + jA;
            int gxB = tx0 - 1 + jB;
            bool okA = rok && ((unsigned)gxA < (unsigned)PP);
            bool okB = rok && ((unsigned)gxB < (unsigned)PP);
            #pragma unroll
            for (int nt = 0; nt < 4; nt++) {
                int ocA = nt * 8 + 2 * t;
                float bA = sb1[ocA], bB = sb1[ocA + 1];
                float y0 = okA ? fmaxf(ah[nt][0] + al[nt][0] * LO_INV + bA, 0.f) : 0.f;
                float y1 = okA ? fmaxf(ah[nt][1] + al[nt][1] * LO_INV + bB, 0.f) : 0.f;
                float y2 = okB ? fmaxf(ah[nt][2] + al[nt][2] * LO_INV + bA, 0.f) : 0.f;
                float y3 = okB ? fmaxf(ah[nt][3] + al[nt][3] * LO_INV + bB, 0.f) : 0.f;
                unsigned vAh, vAl, vBh, vBl;
                split2s(y0, y1, vAh, vAl);
                split2s(y2, y3, vBh, vBl);
                if (jA < C1_W2) {
                    int offA = (nt * C1_NPIX + rr * C1_W2 + jA) * 16 + t * 4;
                    *(unsigned*)(C1H + offA) = vAh;
                    *(unsigned*)(C1L + offA) = vAl;
                }
                if (jB < C1_W2) {
                    int offB = (nt * C1_NPIX + rr * C1_W2 + jB) * 16 + t * 4;
                    *(unsigned*)(C1H + offB) = vBh;
                    *(unsigned*)(C1L + offB) = vBl;
                }
            }
        }
    }
    __syncthreads();

    // ================= conv2 phase (R10 unit, per-kc independent chains) =====
    {
        unsigned w2fh[9][4], w2fl[9][4];
        #pragma unroll
        for (int tap = 0; tap < 9; tap++)
            #pragma unroll
            for (int kc = 0; kc < 4; kc++) {
                w2fh[tap][kc] = W2H[(tap * 4 + kc) * 32 + lane];
                w2fl[tap][kc] = W2L[(tap * 4 + kc) * 32 + lane];
            }

        int y = wid;                 // output row 0..7
        float vb0 = sb2[2 * t];
        float vb1 = sb2[2 * t + 1];
        float rsum = 0.f;

        for (int s = 0; s < 4; s++) {
            float ah[4][4] = {};     // [kc][c] independent chains
            float al[4][4] = {};
            #pragma unroll
            for (int tap = 0; tap < 9; tap++) {
                int ky = tap / 3, kx = tap % 3;
                int j0 = s * 16 + kx + g;
                #pragma unroll
                for (int kc = 0; kc < 4; kc++) {
                    int boff = (kc * C1_NPIX + (y + ky) * C1_W2 + j0) * 16 + t * 4;
                    unsigned a0h = *(const unsigned*)(C1H + boff);
                    unsigned a1h = *(const unsigned*)(C1H + boff + 8 * 16);
                    unsigned a0l = *(const unsigned*)(C1L + boff);
                    unsigned a1l = *(const unsigned*)(C1L + boff + 8 * 16);
                    hmma_16x8x8(ah[kc][0], ah[kc][1], ah[kc][2], ah[kc][3], a0h, a1h, w2fh[tap][kc]);
                    hmma_16x8x8(al[kc][0], al[kc][1], al[kc][2], al[kc][3], a0l, a1l, w2fh[tap][kc]);
                    hmma_16x8x8(al[kc][0], al[kc][1], al[kc][2], al[kc][3], a0h, a1h, w2fl[tap][kc]);
                }
            }
            float c0 = ah[0][0] + ah[1][0] + ah[2][0] + ah[3][0]
                     + (al[0][0] + al[1][0] + al[2][0] + al[3][0]) * LO_INV;
            float c1 = ah[0][1] + ah[1][1] + ah[2][1] + ah[3][1]
                     + (al[0][1] + al[1][1] + al[2][1] + al[3][1]) * LO_INV;
            float c2 = ah[0][2] + ah[1][2] + ah[2][2] + ah[3][2]
                     + (al[0][2] + al[1][2] + al[2][2] + al[3][2]) * LO_INV;
            float c3 = ah[0][3] + ah[1][3] + ah[2][3] + ah[3][3]
                     + (al[0][3] + al[1][3] + al[2][3] + al[3][3]) * LO_INV;

            int gx0 = tx0 + s * 16 + g;
            int gx8 = gx0 + 8;
            float z0 = fmaxf(c0 + vb0, 0.f);
            float z1 = fmaxf(c1 + vb1, 0.f);
            float z2 = fmaxf(c2 + vb0, 0.f);
            float z3 = fmaxf(c3 + vb1, 0.f);
            float v0 = (gx0 < PP) ? value[n * PP + gx0] : 0.f;
            float v8 = (gx8 < PP) ? value[n * PP + gx8] : 0.f;
            rsum += v0 * (z0 + z1) + v8 * (z2 + z3);
        }
        #pragma unroll
        for (int off = 16; off > 0; off >>= 1)
            rsum += __shfl_xor_sync(0xffffffffu, rsum, off);
        int gy = ty0 + y;
        if (lane == 0 && gy < PP)
            g_part[(n * PP + gy) * 15 + blockIdx.x] = rsum;
    }
}

// =====================================================================
// 6) finalize: out[b][p] = (1/8) * sum_tiles partials
// =====================================================================
__global__ void finalize_kernel(float* __restrict__ out)
{
    int i = blockIdx.x * 256 + threadIdx.x;
    if (i >= BB * PP) return;
    float s = 0.f;
    #pragma unroll
    for (int t = 0; t < 15; t++) s += g_part[i * 15 + t];
    out[i] = s * 0.125f;
}

// =====================================================================
extern "C" void kernel_launch(void* const* d_in, const int* in_sizes, int n_in,
                              void* d_out, int out_size)
{
    const float* query = (const float*)d_in[0];
    const float* key_t = (const float*)d_in[1];
    const float* value = (const float*)d_in[2];
    const float* Wq    = (const float*)d_in[3];
    const float* bq    = (const float*)d_in[4];
    const float* Wk    = (const float*)d_in[5];
    const float* bk    = (const float*)d_in[6];
    const float* w1    = (const float*)d_in[7];
    const float* b1    = (const float*)d_in[8];
    const float* w2    = (const float*)d_in[9];
    const float* b2    = (const float*)d_in[10];

    static int smem_set = 0;
    if (!smem_set) {
        cudaFuncSetAttribute(fused_conv_kernel,
                             cudaFuncAttributeMaxDynamicSharedMemorySize, FUSED_SMEM);
        smem_set = 1;
    }

    dim3 gp(57, 8);
    proj_kernel<<<gp, 256>>>(query, Wq, bq, 0);
    proj_kernel<<<gp, 256>>>(key_t, Wk, bk, 1);

    dim3 gs(15, 15, NBH);
    scores_kernel<<<gs, 256>>>();

    dim3 ga(NBH, 8);
    argmax_part_kernel<<<ga, 256>>>();
    dim3 gr(NBH, 4);
    argmax_reduce_kernel<<<gr, 256>>>();

    softmax_kernel<<<NBH * PP, 256>>>();

    dim3 gc(15, 113, BB);
    fused_conv_kernel<<<gc, 256, FUSED_SMEM>>>(w1, b1, w2, b2, value);

    finalize_kernel<<<15, 256>>>((float*)d_out);
}